// round 15
// baseline (speedup 1.0000x reference)
#include <cuda_runtime.h>
#include <math.h>
#include <stdint.h>

namespace {
constexpr int B_   = 64;
constexpr int NV   = 385;
constexpr int NQ   = 321;
constexpr int SS   = 256;
constexpr int NH   = 12;
constexpr int HD   = 64;
constexpr int DIM  = 768;
constexpr int QKVD = 2304;
constexpr int BH   = B_ * NH;
constexpr int TOKENS = B_ * SS;
constexpr float ATT_SCALE = 0.125f;
constexpr float EPS = 1e-6f;
}

__device__ float g_tgt[B_ * DIM];
__device__ float g_tb[B_ * 384];
__device__ float g_h2[(size_t)TOKENS * 192];
__device__ int   g_db[TOKENS];
__device__ float g_q [(size_t)BH * NQ * HD];     // tf32-rounded
__device__ float g_k [(size_t)BH * NV * HD];     // tf32-rounded, xform layout
__device__ float g_v [(size_t)BH * NV * HD];     // tf32-rounded
__device__ float g_ao[(size_t)B_ * NQ * DIM];
__device__ float g_xt [(size_t)B_ * NV * DIM];
__device__ float g_qwt[(size_t)QKVD * DIM];
__device__ float g_pwt[(size_t)DIM * DIM];
__device__ float g_xsl[(size_t)TOKENS * DIM];
__device__ float g_w1h[(size_t)384 * DIM];
__device__ float g_w1l[(size_t)384 * DIM];
__device__ float g_h1h[(size_t)TOKENS * 384];
__device__ float g_h1l[(size_t)TOKENS * 384];
__device__ float g_w2h[(size_t)192 * 384];
__device__ float g_w2l[(size_t)192 * 384];

__device__ __forceinline__ float gelu_exact(float x) {
    return 0.5f * x * (1.0f + erff(x * 0.70710678118654752440f));
}

__device__ __forceinline__ float to_tf32(float x) {
    uint32_t r;
    asm("cvt.rna.tf32.f32 %0, %1;" : "=r"(r) : "f"(x));
    return __uint_as_float(r);
}

__device__ __forceinline__ void mma_tf32(float c[4], const uint32_t a[4],
                                         const uint32_t b[2]) {
    asm volatile(
        "mma.sync.aligned.m16n8k8.row.col.f32.tf32.tf32.f32 "
        "{%0,%1,%2,%3}, {%4,%5,%6,%7}, {%8,%9}, {%0,%1,%2,%3};"
        : "+f"(c[0]), "+f"(c[1]), "+f"(c[2]), "+f"(c[3])
        : "r"(a[0]), "r"(a[1]), "r"(a[2]), "r"(a[3]),
          "r"(b[0]), "r"(b[1]));
}

__device__ __forceinline__ uint32_t smem_u32(const void* p) {
    return (uint32_t)__cvta_generic_to_shared(p);
}
__device__ __forceinline__ void cp_async16(uint32_t dst, const void* src, int src_size) {
    asm volatile("cp.async.cg.shared.global [%0], [%1], 16, %2;"
                 :: "r"(dst), "l"(src), "r"(src_size));
}
#define CP_COMMIT() asm volatile("cp.async.commit_group;")
#define CP_WAIT0()  asm volatile("cp.async.wait_group 0;")
#define CP_WAIT1()  asm volatile("cp.async.wait_group 1;")
#define CP_WAIT2()  asm volatile("cp.async.wait_group 2;")

__device__ __forceinline__ int xfi(int d) {
    return (d & ~15) | ((d & 3) << 2) | ((d >> 2) & 3);
}

// ---------------------------------------------------------------------------
__global__ void xform_kernel(const float* __restrict__ in,
                             float* __restrict__ out, long long ngroups) {
    long long i = blockIdx.x * (long long)blockDim.x + threadIdx.x;
    if (i >= ngroups) return;
    const float4* ip = (const float4*)(in + i * 16);
    float4 a0 = ip[0], a1 = ip[1], a2 = ip[2], a3 = ip[3];
    float4* op = (float4*)(out + i * 16);
    op[0] = make_float4(to_tf32(a0.x), to_tf32(a1.x), to_tf32(a2.x), to_tf32(a3.x));
    op[1] = make_float4(to_tf32(a0.y), to_tf32(a1.y), to_tf32(a2.y), to_tf32(a3.y));
    op[2] = make_float4(to_tf32(a0.z), to_tf32(a1.z), to_tf32(a2.z), to_tf32(a3.z));
    op[3] = make_float4(to_tf32(a0.w), to_tf32(a1.w), to_tf32(a2.w), to_tf32(a3.w));
}

// ---------------------------------------------------------------------------
__global__ void xform_x_kernel(const float* __restrict__ x,
                               float* __restrict__ xt,
                               float* __restrict__ xsl) {
    constexpr int GPR = DIM / 16;
    long long i = blockIdx.x * (long long)blockDim.x + threadIdx.x;
    if (i >= (long long)B_ * NV * GPR) return;
    long long row = i / GPR;
    int grp = (int)(i - row * GPR);
    int b  = (int)(row / NV);
    int nv = (int)(row - (long long)b * NV);
    const float* src = x + (size_t)row * DIM + grp * 16;
    float4 a[4];
    a[0] = ((const float4*)src)[0]; a[1] = ((const float4*)src)[1];
    a[2] = ((const float4*)src)[2]; a[3] = ((const float4*)src)[3];
    float4* dh = (float4*)(xt + (size_t)row * DIM + grp * 16);
    bool srch = (nv >= 129);
    float4* dl = srch
        ? (float4*)(xsl + ((size_t)b * SS + (nv - 129)) * DIM + grp * 16)
        : nullptr;
    #pragma unroll
    for (int u = 0; u < 4; u++) {
        float v0 = (&a[0].x)[u], v1 = (&a[1].x)[u],
              v2 = (&a[2].x)[u], v3 = (&a[3].x)[u];
        float h0 = to_tf32(v0), h1 = to_tf32(v1),
              h2 = to_tf32(v2), h3 = to_tf32(v3);
        dh[u] = make_float4(h0, h1, h2, h3);
        if (srch)
            dl[u] = make_float4(to_tf32(v0 - h0), to_tf32(v1 - h1),
                                to_tf32(v2 - h2), to_tf32(v3 - h3));
    }
}

// ---------------------------------------------------------------------------
__global__ void xform_hl_kernel(const float* __restrict__ in, int ld,
                                float* __restrict__ oh, float* __restrict__ ol,
                                long long nrows, int K) {
    long long i = blockIdx.x * (long long)blockDim.x + threadIdx.x;
    int gpr = K / 16;
    if (i >= nrows * gpr) return;
    long long row = i / gpr;
    int grp = (int)(i - row * gpr);
    const float* src = in + (size_t)row * ld + grp * 16;
    float4 a[4];
    a[0] = ((const float4*)src)[0]; a[1] = ((const float4*)src)[1];
    a[2] = ((const float4*)src)[2]; a[3] = ((const float4*)src)[3];
    float* dh = oh + (size_t)row * K + grp * 16;
    float* dl = ol + (size_t)row * K + grp * 16;
    #pragma unroll
    for (int u = 0; u < 4; u++) {
        float v0 = (&a[0].x)[u], v1 = (&a[1].x)[u],
              v2 = (&a[2].x)[u], v3 = (&a[3].x)[u];
        float h0 = to_tf32(v0), h1 = to_tf32(v1),
              h2 = to_tf32(v2), h3 = to_tf32(v3);
        ((float4*)dh)[u] = make_float4(h0, h1, h2, h3);
        ((float4*)dl)[u] = make_float4(to_tf32(v0 - h0), to_tf32(v1 - h1),
                                       to_tf32(v2 - h2), to_tf32(v3 - h3));
    }
}

// ---------------------------------------------------------------------------
// cp.async 3-stage TF32 GEMM, 128x128 block tile, FOUR warps of 64x64.
// 128 threads, 2 blocks/SM (96KB smem each). K % 32 == 0.
// MODE: 0 bias+store, 2 qkv scatter (q/k/v tf32-rounded; K xform layout)
// ---------------------------------------------------------------------------
template<int MODE>
__global__ void __launch_bounds__(128, 2)
tc_gemm_async(const float* __restrict__ A, const float* __restrict__ B,
              const float* __restrict__ bias, float* __restrict__ C,
              int M, int N, int K)
{
    extern __shared__ float smx[];

    const int m0 = blockIdx.y * 128;
    const int n0 = blockIdx.x * 128;
    const int tid  = threadIdx.x;
    const int lane = tid & 31;
    const int w    = tid >> 5;          // 0..3
    const int wm = w >> 1, wn = w & 1;
    const int g  = lane >> 2, tg = lane & 3;
    const int m0w = wm * 64, n0w = wn * 64;

    const int crow = tid >> 3;          // 0..15
    const int cu   = tid & 7;
    const int fswz = ((g & 1) << 2) | (g & 3);

    float acc[4][8][4];
    #pragma unroll
    for (int i = 0; i < 4; i++)
        #pragma unroll
        for (int j = 0; j < 8; j++)
            #pragma unroll
            for (int r = 0; r < 4; r++) acc[i][j][r] = 0.f;

    auto issue = [&](int k0, int st) {
        float* sa = smx + st * 8192;
        float* sb = sa + 4096;
        #pragma unroll
        for (int i = 0; i < 8; i++) {
            int row = crow + 16 * i;
            int pu  = cu ^ (((row & 1) << 2) | (row & 3));
            int gm  = m0 + row;
            int gmc = gm < M ? gm : M - 1;
            cp_async16(smem_u32(sa + row * 32 + pu * 4),
                       A + (size_t)gmc * K + k0 + cu * 4, gm < M ? 16 : 0);
            int gn  = n0 + row;
            int gnc = gn < N ? gn : N - 1;
            cp_async16(smem_u32(sb + row * 32 + pu * 4),
                       B + (size_t)gnc * K + k0 + cu * 4, gn < N ? 16 : 0);
        }
        CP_COMMIT();
    };

    const int T = K / 32;
    issue(0, 0);
    issue(32, 1);
    for (int t = 0; t < T; t++) {
        if (t + 2 < T) issue((t + 2) * 32, (t + 2) % 3);
        else           CP_COMMIT();
        CP_WAIT2();
        __syncthreads();

        const float* sa = smx + (t % 3) * 8192;
        const float* sb = sa + 4096;
        #pragma unroll
        for (int gq = 0; gq < 2; gq++) {
            const int pu4 = ((4 * gq + tg) ^ fswz) * 4;
            float4 va[8];
            #pragma unroll
            for (int i = 0; i < 8; i++)
                va[i] = *(const float4*)(sa + (m0w + g + 8*i) * 32 + pu4);
            float4 vb[8];
            #pragma unroll
            for (int j = 0; j < 8; j++)
                vb[j] = *(const float4*)(sb + (n0w + 8*j + g) * 32 + pu4);

            #pragma unroll
            for (int i = 0; i < 4; i++) {
                uint32_t a0[4] = {
                    __float_as_uint(va[2*i].x), __float_as_uint(va[2*i+1].x),
                    __float_as_uint(va[2*i].y), __float_as_uint(va[2*i+1].y)};
                uint32_t a8[4] = {
                    __float_as_uint(va[2*i].z), __float_as_uint(va[2*i+1].z),
                    __float_as_uint(va[2*i].w), __float_as_uint(va[2*i+1].w)};
                #pragma unroll
                for (int j = 0; j < 8; j++) {
                    uint32_t b0[2] = {__float_as_uint(vb[j].x), __float_as_uint(vb[j].y)};
                    uint32_t b8[2] = {__float_as_uint(vb[j].z), __float_as_uint(vb[j].w)};
                    mma_tf32(acc[i][j], a0, b0);
                    mma_tf32(acc[i][j], a8, b8);
                }
            }
        }
        __syncthreads();
    }

    #pragma unroll
    for (int i = 0; i < 4; i++) {
        #pragma unroll
        for (int rr = 0; rr < 2; rr++) {
            const int gm = m0 + m0w + i*16 + g + rr*8;
            if (gm >= M) continue;
            if (MODE == 0) {
                float* crowp = C + (size_t)gm * N;
                #pragma unroll
                for (int j = 0; j < 8; j++) {
                    int gn = n0 + n0w + j*8 + tg*2;
                    crowp[gn]   = acc[i][j][rr*2]   + bias[gn];
                    crowp[gn+1] = acc[i][j][rr*2+1] + bias[gn+1];
                }
            } else {
                const int bb = gm / NV;
                const int nv = gm - bb * NV;
                const int qi = (nv == 0) ? 0 : (nv >= 65 ? nv - 64 : -1);
                float* kB = g_k + (size_t)bb * NH * NV * HD + (size_t)nv * HD;
                float* vB = g_v + (size_t)bb * NH * NV * HD + (size_t)nv * HD;
                float* qB = (qi >= 0)
                    ? g_q + (size_t)bb * NH * NQ * HD + (size_t)qi * HD : nullptr;
                #pragma unroll
                for (int j = 0; j < 8; j++) {
                    #pragma unroll
                    for (int e = 0; e < 2; e++) {
                        int gn = n0 + n0w + j*8 + tg*2 + e;
                        float t = to_tf32(acc[i][j][rr*2 + e] + bias[gn]);
                        int typ = gn / DIM;
                        int hd  = gn - typ * DIM;
                        int h = hd >> 6, d = hd & 63;
                        if (typ == 1) {
                            kB[(size_t)h * NV * HD + xfi(d)] = t;
                        } else if (typ == 2) {
                            vB[(size_t)h * NV * HD + d] = t;
                        } else if (qB) {
                            qB[(size_t)h * NQ * HD + d] = t;
                        }
                    }
                }
            }
        }
    }
}

// ---------------------------------------------------------------------------
// cp.async 2-stage 3xTF32 GEMM + GELU (unchanged from R14).
// ---------------------------------------------------------------------------
template<int HLOUT, int AGATHER>
__global__ void __launch_bounds__(256, 2)
tc_gemm3x_async(const float* __restrict__ Ah_, const float* __restrict__ Al_,
                const float* __restrict__ Bh_, const float* __restrict__ Bl_,
                const float* __restrict__ bias,
                float* __restrict__ C, float* __restrict__ ol,
                int M, int N, int K)
{
    extern __shared__ float smx[];

    const int m0 = blockIdx.y * 128;
    const int n0 = blockIdx.x * 128;
    const int tid  = threadIdx.x;
    const int lane = tid & 31;
    const int w    = tid >> 5;
    const int wm = w >> 1, wn = w & 1;
    const int g  = lane >> 2, tg = lane & 3;
    const int m0w = wm * 32, n0w = wn * 64;

    const int crow = tid >> 2;
    const int cu   = tid & 3;
    const int pu4  = (tg ^ (g & 3)) * 4;

    float acc[2][8][4];
    #pragma unroll
    for (int i = 0; i < 2; i++)
        #pragma unroll
        for (int j = 0; j < 8; j++)
            #pragma unroll
            for (int r = 0; r < 4; r++) acc[i][j][r] = 0.f;

    auto issue = [&](int k0, int st) {
        float* s_ah = smx + st * 8192;
        float* s_al = s_ah + 2048;
        float* s_bh = s_al + 2048;
        float* s_bl = s_bh + 2048;
        #pragma unroll
        for (int i = 0; i < 2; i++) {
            int row = crow + 64 * i;
            int pu  = cu ^ (row & 3);
            int gm  = m0 + row;
            size_t ahoff;
            if (AGATHER == 1) {
                int b = gm >> 8, s = gm & 255;
                ahoff = ((size_t)b * NV + 129 + s) * DIM + k0 + cu * 4;
            } else {
                ahoff = (size_t)gm * K + k0 + cu * 4;
            }
            size_t aloff = (size_t)gm * K + k0 + cu * 4;
            cp_async16(smem_u32(s_ah + row * 16 + pu * 4), Ah_ + ahoff, 16);
            cp_async16(smem_u32(s_al + row * 16 + pu * 4), Al_ + aloff, 16);
            int gn  = n0 + row;
            int gnc = gn < N ? gn : N - 1;
            int sz  = gn < N ? 16 : 0;
            size_t boff = (size_t)gnc * K + k0 + cu * 4;
            cp_async16(smem_u32(s_bh + row * 16 + pu * 4), Bh_ + boff, sz);
            cp_async16(smem_u32(s_bl + row * 16 + pu * 4), Bl_ + boff, sz);
        }
        CP_COMMIT();
    };

    const int T = K / 16;
    issue(0, 0);
    for (int t = 0; t < T; t++) {
        if (t + 1 < T) issue((t + 1) * 16, (t + 1) & 1);
        else           CP_COMMIT();
        CP_WAIT1();
        __syncthreads();

        const float* s    = smx + (t & 1) * 8192;
        const float* s_ah = s;
        const float* s_al = s + 2048;
        const float* s_bh = s + 4096;
        const float* s_bl = s + 6144;

        float4 vah[4], val_[4];
        #pragma unroll
        for (int i = 0; i < 4; i++) {
            int row = m0w + g + 8*i;
            vah[i]  = *(const float4*)(s_ah + row * 16 + pu4);
            val_[i] = *(const float4*)(s_al + row * 16 + pu4);
        }
        #pragma unroll
        for (int j = 0; j < 8; j++) {
            int row = n0w + j*8 + g;
            float4 vbh = *(const float4*)(s_bh + row * 16 + pu4);
            float4 vbl = *(const float4*)(s_bl + row * 16 + pu4);
            uint32_t bh0[2] = {__float_as_uint(vbh.x), __float_as_uint(vbh.y)};
            uint32_t bh8[2] = {__float_as_uint(vbh.z), __float_as_uint(vbh.w)};
            uint32_t bl0[2] = {__float_as_uint(vbl.x), __float_as_uint(vbl.y)};
            uint32_t bl8[2] = {__float_as_uint(vbl.z), __float_as_uint(vbl.w)};
            #pragma unroll
            for (int i = 0; i < 2; i++) {
                uint32_t ah0[4] = {
                    __float_as_uint(vah[2*i].x), __float_as_uint(vah[2*i+1].x),
                    __float_as_uint(vah[2*i].y), __float_as_uint(vah[2*i+1].y)};
                uint32_t ah8[4] = {
                    __float_as_uint(vah[2*i].z), __float_as_uint(vah[2*i+1].z),
                    __float_as_uint(vah[2*i].w), __float_as_uint(vah[2*i+1].w)};
                uint32_t al0[4] = {
                    __float_as_uint(val_[2*i].x), __float_as_uint(val_[2*i+1].x),
                    __float_as_uint(val_[2*i].y), __float_as_uint(val_[2*i+1].y)};
                uint32_t al8[4] = {
                    __float_as_uint(val_[2*i].z), __float_as_uint(val_[2*i+1].z),
                    __float_as_uint(val_[2*i].w), __float_as_uint(val_[2*i+1].w)};
                mma_tf32(acc[i][j], ah0, bl0);
                mma_tf32(acc[i][j], al0, bh0);
                mma_tf32(acc[i][j], ah0, bh0);
                mma_tf32(acc[i][j], ah8, bl8);
                mma_tf32(acc[i][j], al8, bh8);
                mma_tf32(acc[i][j], ah8, bh8);
            }
        }
        __syncthreads();
    }

    #pragma unroll
    for (int i = 0; i < 2; i++) {
        #pragma unroll
        for (int rr = 0; rr < 2; rr++) {
            int gm = m0 + m0w + i*16 + g + rr*8;
            if (gm >= M) continue;
            const float* brow = (HLOUT == 1) ? g_tb + (gm >> 8) * 384 : bias;
            #pragma unroll
            for (int j = 0; j < 8; j++) {
                #pragma unroll
                for (int e = 0; e < 2; e++) {
                    int gn = n0 + n0w + j*8 + tg*2 + e;
                    if (gn >= N) continue;
                    float t = gelu_exact(acc[i][j][rr*2+e] + brow[gn]);
                    if (HLOUT == 1) {
                        int dt = xfi(gn & 15) | (gn & ~15);
                        float th = to_tf32(t);
                        C [(size_t)gm * N + dt] = th;
                        ol[(size_t)gm * N + dt] = to_tf32(t - th);
                    } else {
                        C[(size_t)gm * N + gn] = t;
                    }
                }
            }
        }
    }
}

// ---------------------------------------------------------------------------
__global__ void tb_kernel(const float* __restrict__ dp1_w,
                          const float* __restrict__ dp1_b) {
    int b = blockIdx.x;
    int n = threadIdx.x;
    const float* tg = g_tgt + (size_t)b * DIM;
    const float* wr = dp1_w + (size_t)n * 1536 + DIM;
    float s = dp1_b[n];
    #pragma unroll 8
    for (int k = 0; k < DIM; k++)
        s = fmaf(tg[k], wr[k], s);
    g_tb[b * 384 + n] = s;
}

// ---------------------------------------------------------------------------
// Flash attention v4: cp.async staging + in-kernel V column sums (vsum fused).
// ---------------------------------------------------------------------------
namespace {
constexpr int BQ = 128, BKV = 64;
}

struct FlashSmem {
    float Ks[BKV * HD];        // xform rows, unit-swizzled (pu = u ^ (kv&7))
    float Vs[BKV][HD + 4];
    float Ps[BKV][BQ + 4];     // also Q staging and final vsum reduce area
    int   km[BKV];
};

__global__ void __launch_bounds__(256, 2)
flash_kernel() {
    extern __shared__ char raw_smem[];
    FlashSmem& S = *reinterpret_cast<FlashSmem*>(raw_smem);

    const int bh = blockIdx.y;
    const int b  = bh / NH, h = bh % NH;
    const int q0 = blockIdx.x * BQ;
    const int tid  = threadIdx.x;
    const int lane = tid & 31;
    const int w    = tid >> 5;
    const int g  = lane >> 2, tg = lane & 3;
    const int mw = w * 16;
    const int* db = g_db + (size_t)b * SS;

    #pragma unroll
    for (int it = 0; it < 8; it++) {
        int idx = tid + it * 256;
        int q  = idx >> 4;
        int dc = (idx & 15) * 4;
        int gq = q0 + q;
        float4 v = make_float4(0.f, 0.f, 0.f, 0.f);
        if (gq < NQ)
            v = *(const float4*)(g_q + ((size_t)bh*NQ + gq)*HD + dc);
        S.Ps[dc+0][q] = v.x * ATT_SCALE;
        S.Ps[dc+1][q] = v.y * ATT_SCALE;
        S.Ps[dc+2][q] = v.z * ATT_SCALE;
        S.Ps[dc+3][q] = v.w * ATT_SCALE;
    }
    __syncthreads();

    uint32_t qa[8][4];
    #pragma unroll
    for (int s = 0; s < 8; s++) {
        int kk = s * 8;
        qa[s][0] = __float_as_uint(S.Ps[kk+tg  ][mw + g    ]);
        qa[s][1] = __float_as_uint(S.Ps[kk+tg  ][mw + g + 8]);
        qa[s][2] = __float_as_uint(S.Ps[kk+tg+4][mw + g    ]);
        qa[s][3] = __float_as_uint(S.Ps[kk+tg+4][mw + g + 8]);
    }

    const int r0 = q0 + mw + g, r1 = r0 + 8;
    const bool qT0 = (r0 >= 1 && r0 <= 64);
    const bool qT1 = (r1 >= 1 && r1 <= 64);
    const bool qP0 = (r0 >= 65 && r0 < NQ) ? (db[r0 - 65] != 0) : false;
    const bool qP1 = (r1 >= 65 && r1 < NQ) ? (db[r1 - 65] != 0) : false;

    float m0 = -INFINITY, m1 = -INFINITY, l0 = 0.f, l1 = 0.f;
    float accO[8][4];
    #pragma unroll
    for (int j = 0; j < 8; j++)
        #pragma unroll
        for (int r = 0; r < 4; r++) accO[j][r] = 0.f;

    // vsum partials: thread handles column (tid&63), row group (tid>>6)
    const int vdcol = tid & 63;
    const int vrgrp = tid >> 6;
    float vreg = 0.f;

    for (int kt = 0; kt < 7; kt++) {
        __syncthreads();
        const int kbase = kt * BKV;
        #pragma unroll
        for (int it = 0; it < 4; it++) {
            int idx = tid + it * 256;
            int kv  = idx >> 4;
            int u   = idx & 15;
            int k   = kbase + kv;
            int kc  = (k < NV) ? k : NV - 1;
            int sz  = (k < NV) ? 16 : 0;
            int pu  = u ^ (kv & 7);
            cp_async16(smem_u32(S.Ks + kv * HD + pu * 4),
                       g_k + ((size_t)bh*NV + kc)*HD + u*4, sz);
            cp_async16(smem_u32(&S.Vs[kv][u*4]),
                       g_v + ((size_t)bh*NV + kc)*HD + u*4, sz);
        }
        CP_COMMIT();
        if (tid < BKV) {
            int k = kbase + tid;
            int fl = 0;
            if (k < NV) {
                fl = 4;
                if (k >= 1 && k <= 128) fl |= 1;
                if (k >= 129 && db[k - 129] != 0) fl |= 2;
            }
            S.km[tid] = fl;
        }
        CP_WAIT0();
        __syncthreads();

        // accumulate V column sums (valid rows only)
        {
            int kvmax = NV - kbase;       // rows valid in this tile
            #pragma unroll
            for (int rr2 = 0; rr2 < 16; rr2++) {
                int kv = vrgrp * 16 + rr2;
                if (kv < kvmax) vreg += S.Vs[kv][vdcol];
            }
        }

        float sacc[8][4];
        #pragma unroll
        for (int j = 0; j < 8; j++)
            #pragma unroll
            for (int r = 0; r < 4; r++) sacc[j][r] = 0.f;

        #pragma unroll
        for (int j = 0; j < 8; j++) {
            const int row = j*8 + g;
            const float* kr = S.Ks + row * HD;
            const int sw = row & 7;
            float4 kb[4];
            #pragma unroll
            for (int grp = 0; grp < 4; grp++)
                kb[grp] = *(const float4*)(kr + (((grp << 2) | tg) ^ sw) * 4);
            #pragma unroll
            for (int s = 0; s < 8; s++) {
                int grp = s >> 1;
                uint32_t b2[2];
                if (s & 1) {
                    b2[0] = __float_as_uint(kb[grp].z);
                    b2[1] = __float_as_uint(kb[grp].w);
                } else {
                    b2[0] = __float_as_uint(kb[grp].x);
                    b2[1] = __float_as_uint(kb[grp].y);
                }
                mma_tf32(sacc[j], qa[s], b2);
            }
        }

        int fA[8], fB[8];
        float tm0 = -INFINITY, tm1 = -INFINITY;
        #pragma unroll
        for (int j = 0; j < 8; j++) {
            int kvA = j*8 + 2*tg;
            fA[j] = S.km[kvA];
            fB[j] = S.km[kvA + 1];
            if (fA[j] & 4) { tm0 = fmaxf(tm0, sacc[j][0]); tm1 = fmaxf(tm1, sacc[j][2]); }
            if (fB[j] & 4) { tm0 = fmaxf(tm0, sacc[j][1]); tm1 = fmaxf(tm1, sacc[j][3]); }
        }
        #pragma unroll
        for (int o = 1; o <= 2; o <<= 1) {
            tm0 = fmaxf(tm0, __shfl_xor_sync(0xffffffffu, tm0, o));
            tm1 = fmaxf(tm1, __shfl_xor_sync(0xffffffffu, tm1, o));
        }
        float nm0 = fmaxf(m0, tm0), nm1 = fmaxf(m1, tm1);
        float f0 = __expf(m0 - nm0), f1 = __expf(m1 - nm1);

        float rs0 = 0.f, rs1 = 0.f;
        #pragma unroll
        for (int j = 0; j < 8; j++) {
            bool mA0 = (fA[j] & 4) && !((qT0 && (fA[j] & 2)) || (qP0 && (fA[j] & 1)));
            bool mB0 = (fB[j] & 4) && !((qT0 && (fB[j] & 2)) || (qP0 && (fB[j] & 1)));
            bool mA1 = (fA[j] & 4) && !((qT1 && (fA[j] & 2)) || (qP1 && (fA[j] & 1)));
            bool mB1 = (fB[j] & 4) && !((qT1 && (fB[j] & 2)) || (qP1 && (fB[j] & 1)));
            float e00 = mA0 ? __expf(sacc[j][0] - nm0) : 0.f;
            float e01 = mB0 ? __expf(sacc[j][1] - nm0) : 0.f;
            float e10 = mA1 ? __expf(sacc[j][2] - nm1) : 0.f;
            float e11 = mB1 ? __expf(sacc[j][3] - nm1) : 0.f;
            rs0 += e00 + e01;
            rs1 += e10 + e11;
            int kvA = j*8 + 2*tg;
            S.Ps[kvA    ][mw + g    ] = to_tf32(e00);
            S.Ps[kvA + 1][mw + g    ] = to_tf32(e01);
            S.Ps[kvA    ][mw + g + 8] = to_tf32(e10);
            S.Ps[kvA + 1][mw + g + 8] = to_tf32(e11);
        }
        #pragma unroll
        for (int o = 1; o <= 2; o <<= 1) {
            rs0 += __shfl_xor_sync(0xffffffffu, rs0, o);
            rs1 += __shfl_xor_sync(0xffffffffu, rs1, o);
        }
        l0 = l0 * f0 + rs0;
        l1 = l1 * f1 + rs1;
        #pragma unroll
        for (int j = 0; j < 8; j++) {
            accO[j][0] *= f0; accO[j][1] *= f0;
            accO[j][2] *= f1; accO[j][3] *= f1;
        }
        m0 = nm0; m1 = nm1;
        __syncwarp();

        #pragma unroll
        for (int kk = 0; kk < BKV; kk += 8) {
            uint32_t a[4];
            a[0] = __float_as_uint(S.Ps[kk+tg  ][mw + g    ]);
            a[1] = __float_as_uint(S.Ps[kk+tg  ][mw + g + 8]);
            a[2] = __float_as_uint(S.Ps[kk+tg+4][mw + g    ]);
            a[3] = __float_as_uint(S.Ps[kk+tg+4][mw + g + 8]);
            #pragma unroll
            for (int j = 0; j < 8; j++) {
                uint32_t b2[2] = {
                    __float_as_uint(S.Vs[kk+tg  ][j*8 + g]),
                    __float_as_uint(S.Vs[kk+tg+4][j*8 + g])};
                mma_tf32(accO[j], a, b2);
            }
        }
    }

    // reduce vsum partials through (now free) Ps region
    __syncthreads();
    float* vps = (float*)S.Ps;
    vps[vrgrp * 64 + vdcol] = vreg;
    __syncthreads();

    const float inv0 = 1.f / (l0 + EPS);
    const float inv1 = 1.f / (l1 + EPS);
    const float c = EPS / (float)NQ;
    #pragma unroll
    for (int j = 0; j < 8; j++) {
        #pragma unroll
        for (int r = 0; r < 4; r++) {
            int d = j*8 + 2*tg + (r & 1);
            int q = q0 + mw + g + ((r & 2) ? 8 : 0);
            if (q >= NQ) continue;
            float vs = vps[d] + vps[64 + d] + vps[128 + d] + vps[192 + d];
            float val = (accO[j][r] + c * vs) * ((r & 2) ? inv1 : inv0);
            int dt = xfi(d);
            g_ao[((size_t)b*NQ + q)*DIM + h*HD + dt] = to_tf32(val);
        }
    }
}

// ---------------------------------------------------------------------------
__global__ void mean_kernel(const float* __restrict__ x) {
    int b = blockIdx.x;
    int c = threadIdx.x;
    float s = 0.f;
    #pragma unroll 8
    for (int t = 0; t < 64; t++)
        s += x[((size_t)b*NV + 65 + t)*DIM + c];
    g_tgt[b*DIM + c] = s * (1.0f/64.0f);
}

__global__ void mlp3_kernel(const float* __restrict__ w3,
                            const float* __restrict__ b3) {
    int gwarp = (blockIdx.x * blockDim.x + threadIdx.x) >> 5;
    int lane  = threadIdx.x & 31;
    if (gwarp >= TOKENS) return;
    const float* row = g_h2 + (size_t)gwarp * 192;
    float s0 = 0.f, s1 = 0.f;
    for (int k = lane; k < 192; k += 32) {
        float xv = row[k];
        s0 = fmaf(xv, w3[k],       s0);
        s1 = fmaf(xv, w3[192 + k], s1);
    }
    #pragma unroll
    for (int o = 16; o; o >>= 1) {
        s0 += __shfl_xor_sync(0xffffffffu, s0, o);
        s1 += __shfl_xor_sync(0xffffffffu, s1, o);
    }
    if (lane == 0)
        g_db[gwarp] = (s0 + b3[0] >= s1 + b3[1]) ? 1 : 0;
}

// ---------------------------------------------------------------------------
extern "C" void kernel_launch(void* const* d_in, const int* in_sizes, int n_in,
                              void* d_out, int out_size) {
    const float* x      = (const float*)d_in[0];
    const float* qkv_w  = (const float*)d_in[2];
    const float* qkv_b  = (const float*)d_in[3];
    const float* proj_w = (const float*)d_in[4];
    const float* proj_b = (const float*)d_in[5];
    const float* dp1_w  = (const float*)d_in[6];
    const float* dp1_b  = (const float*)d_in[7];
    const float* dp2_w  = (const float*)d_in[8];
    const float* dp2_b  = (const float*)d_in[9];
    const float* dp3_w  = (const float*)d_in[10];
    const float* dp3_b  = (const float*)d_in[11];
    float* out = (float*)d_out;

    float *p_h2, *p_ao, *p_xt, *p_qwt, *p_pwt;
    float *p_xsl, *p_w1h, *p_w1l, *p_h1h, *p_h1l, *p_w2h, *p_w2l;
    cudaGetSymbolAddress((void**)&p_h2,  g_h2);
    cudaGetSymbolAddress((void**)&p_ao,  g_ao);
    cudaGetSymbolAddress((void**)&p_xt,  g_xt);
    cudaGetSymbolAddress((void**)&p_qwt, g_qwt);
    cudaGetSymbolAddress((void**)&p_pwt, g_pwt);
    cudaGetSymbolAddress((void**)&p_xsl, g_xsl);
    cudaGetSymbolAddress((void**)&p_w1h, g_w1h);
    cudaGetSymbolAddress((void**)&p_w1l, g_w1l);
    cudaGetSymbolAddress((void**)&p_h1h, g_h1h);
    cudaGetSymbolAddress((void**)&p_h1l, g_h1l);
    cudaGetSymbolAddress((void**)&p_w2h, g_w2h);
    cudaGetSymbolAddress((void**)&p_w2l, g_w2l);

    auto cdiv = [](int a, int b) { return (a + b - 1) / b; };

    constexpr int SMEMAS3 = 3 * 8192 * 4;
    constexpr int SMEM3XA = 2 * 8192 * 4;
    cudaFuncSetAttribute(tc_gemm_async<2>,
                         cudaFuncAttributeMaxDynamicSharedMemorySize, SMEMAS3);
    cudaFuncSetAttribute(tc_gemm_async<0>,
                         cudaFuncAttributeMaxDynamicSharedMemorySize, SMEMAS3);
    cudaFuncSetAttribute((const void*)tc_gemm3x_async<1,1>,
                         cudaFuncAttributeMaxDynamicSharedMemorySize, SMEM3XA);
    cudaFuncSetAttribute((const void*)tc_gemm3x_async<0,0>,
                         cudaFuncAttributeMaxDynamicSharedMemorySize, SMEM3XA);
    cudaFuncSetAttribute(flash_kernel,
                         cudaFuncAttributeMaxDynamicSharedMemorySize,
                         (int)sizeof(FlashSmem));

    {
        long long gx = (long long)B_ * NV * (DIM / 16);
        xform_x_kernel<<<(unsigned)cdiv((int)gx, 256), 256>>>(x, p_xt, p_xsl);
        long long gw = (long long)QKVD * (DIM / 16);
        xform_kernel<<<(unsigned)cdiv((int)gw, 256), 256>>>(qkv_w, p_qwt, gw);
        long long gp = (long long)DIM * (DIM / 16);
        xform_kernel<<<(unsigned)cdiv((int)gp, 256), 256>>>(proj_w, p_pwt, gp);
        long long g1 = 384LL * (DIM / 16);
        xform_hl_kernel<<<(unsigned)cdiv((int)g1, 256), 256>>>(
            dp1_w, 1536, p_w1h, p_w1l, 384, DIM);
        long long g2 = 192LL * (384 / 16);
        xform_hl_kernel<<<(unsigned)cdiv((int)g2, 256), 256>>>(
            dp2_w, 384, p_w2h, p_w2l, 192, 384);
    }

    mean_kernel<<<B_, DIM>>>(x);
    tb_kernel<<<B_, 384>>>(dp1_w, dp1_b);
    tc_gemm3x_async<1,1><<<dim3(3, TOKENS/128), 256, SMEM3XA>>>(
        p_xt, p_xsl, p_w1h, p_w1l, nullptr, p_h1h, p_h1l, TOKENS, 384, DIM);
    tc_gemm3x_async<0,0><<<dim3(2, TOKENS/128), 256, SMEM3XA>>>(
        p_h1h, p_h1l, p_w2h, p_w2l, dp2_b, p_h2, nullptr, TOKENS, 192, 384);
    mlp3_kernel<<<cdiv(TOKENS*32, 256), 256>>>(dp3_w, dp3_b);

    // QKV projection + head scatter (4-warp 128x128, 3-stage, 2 blocks/SM)
    tc_gemm_async<2><<<dim3(QKVD/128, cdiv(B_*NV,128)), 128, SMEMAS3>>>(
        p_xt, p_qwt, qkv_b, nullptr, B_*NV, QKVD, DIM);

    // fused attention (includes V column sums)
    flash_kernel<<<dim3(cdiv(NQ, BQ), BH), 256, sizeof(FlashSmem)>>>();

    // output projection
    tc_gemm_async<0><<<dim3(DIM/128, cdiv(B_*NQ,128)), 128, SMEMAS3>>>(
        p_ao, p_pwt, proj_b, out, B_*NQ, DIM, DIM);
}

// round 16
// speedup vs baseline: 1.0357x; 1.0357x over previous
#include <cuda_runtime.h>
#include <math.h>
#include <stdint.h>

namespace {
constexpr int B_   = 64;
constexpr int NV   = 385;
constexpr int NQ   = 321;
constexpr int SS   = 256;
constexpr int NH   = 12;
constexpr int HD   = 64;
constexpr int DIM  = 768;
constexpr int QKVD = 2304;
constexpr int BH   = B_ * NH;
constexpr int TOKENS = B_ * SS;
constexpr float ATT_SCALE = 0.125f;
constexpr float EPS = 1e-6f;
}

__device__ float g_tgt[B_ * DIM];
__device__ float g_tb[B_ * 384];
__device__ float g_h2[(size_t)TOKENS * 192];
__device__ int   g_db[TOKENS];
__device__ float g_q [(size_t)BH * NQ * HD];     // tf32-rounded
__device__ float g_k [(size_t)BH * NV * HD];     // tf32-rounded, xform layout
__device__ float g_v [(size_t)BH * NV * HD];     // tf32-rounded
__device__ float g_ao[(size_t)B_ * NQ * DIM];
__device__ float g_xt [(size_t)B_ * NV * DIM];
__device__ float g_qwt[(size_t)QKVD * DIM];
__device__ float g_pwt[(size_t)DIM * DIM];
__device__ float g_xsl[(size_t)TOKENS * DIM];
__device__ float g_w1h[(size_t)384 * DIM];
__device__ float g_w1l[(size_t)384 * DIM];
__device__ float g_h1h[(size_t)TOKENS * 384];
__device__ float g_h1l[(size_t)TOKENS * 384];
__device__ float g_w2h[(size_t)192 * 384];
__device__ float g_w2l[(size_t)192 * 384];

__device__ __forceinline__ float gelu_exact(float x) {
    return 0.5f * x * (1.0f + erff(x * 0.70710678118654752440f));
}

__device__ __forceinline__ float to_tf32(float x) {
    uint32_t r;
    asm("cvt.rna.tf32.f32 %0, %1;" : "=r"(r) : "f"(x));
    return __uint_as_float(r);
}

__device__ __forceinline__ void mma_tf32(float c[4], const uint32_t a[4],
                                         const uint32_t b[2]) {
    asm volatile(
        "mma.sync.aligned.m16n8k8.row.col.f32.tf32.tf32.f32 "
        "{%0,%1,%2,%3}, {%4,%5,%6,%7}, {%8,%9}, {%0,%1,%2,%3};"
        : "+f"(c[0]), "+f"(c[1]), "+f"(c[2]), "+f"(c[3])
        : "r"(a[0]), "r"(a[1]), "r"(a[2]), "r"(a[3]),
          "r"(b[0]), "r"(b[1]));
}

__device__ __forceinline__ uint32_t smem_u32(const void* p) {
    return (uint32_t)__cvta_generic_to_shared(p);
}
__device__ __forceinline__ void cp_async16(uint32_t dst, const void* src, int src_size) {
    asm volatile("cp.async.cg.shared.global [%0], [%1], 16, %2;"
                 :: "r"(dst), "l"(src), "r"(src_size));
}
#define CP_COMMIT() asm volatile("cp.async.commit_group;")
#define CP_WAIT0()  asm volatile("cp.async.wait_group 0;")
#define CP_WAIT1()  asm volatile("cp.async.wait_group 1;")
#define CP_WAIT2()  asm volatile("cp.async.wait_group 2;")

__device__ __forceinline__ int xfi(int d) {
    return (d & ~15) | ((d & 3) << 2) | ((d >> 2) & 3);
}

// ---------------------------------------------------------------------------
__global__ void xform_kernel(const float* __restrict__ in,
                             float* __restrict__ out, long long ngroups) {
    long long i = blockIdx.x * (long long)blockDim.x + threadIdx.x;
    if (i >= ngroups) return;
    const float4* ip = (const float4*)(in + i * 16);
    float4 a0 = ip[0], a1 = ip[1], a2 = ip[2], a3 = ip[3];
    float4* op = (float4*)(out + i * 16);
    op[0] = make_float4(to_tf32(a0.x), to_tf32(a1.x), to_tf32(a2.x), to_tf32(a3.x));
    op[1] = make_float4(to_tf32(a0.y), to_tf32(a1.y), to_tf32(a2.y), to_tf32(a3.y));
    op[2] = make_float4(to_tf32(a0.z), to_tf32(a1.z), to_tf32(a2.z), to_tf32(a3.z));
    op[3] = make_float4(to_tf32(a0.w), to_tf32(a1.w), to_tf32(a2.w), to_tf32(a3.w));
}

// ---------------------------------------------------------------------------
__global__ void xform_x_kernel(const float* __restrict__ x,
                               float* __restrict__ xt,
                               float* __restrict__ xsl) {
    constexpr int GPR = DIM / 16;
    long long i = blockIdx.x * (long long)blockDim.x + threadIdx.x;
    if (i >= (long long)B_ * NV * GPR) return;
    long long row = i / GPR;
    int grp = (int)(i - row * GPR);
    int b  = (int)(row / NV);
    int nv = (int)(row - (long long)b * NV);
    const float* src = x + (size_t)row * DIM + grp * 16;
    float4 a[4];
    a[0] = ((const float4*)src)[0]; a[1] = ((const float4*)src)[1];
    a[2] = ((const float4*)src)[2]; a[3] = ((const float4*)src)[3];
    float4* dh = (float4*)(xt + (size_t)row * DIM + grp * 16);
    bool srch = (nv >= 129);
    float4* dl = srch
        ? (float4*)(xsl + ((size_t)b * SS + (nv - 129)) * DIM + grp * 16)
        : nullptr;
    #pragma unroll
    for (int u = 0; u < 4; u++) {
        float v0 = (&a[0].x)[u], v1 = (&a[1].x)[u],
              v2 = (&a[2].x)[u], v3 = (&a[3].x)[u];
        float h0 = to_tf32(v0), h1 = to_tf32(v1),
              h2 = to_tf32(v2), h3 = to_tf32(v3);
        dh[u] = make_float4(h0, h1, h2, h3);
        if (srch)
            dl[u] = make_float4(to_tf32(v0 - h0), to_tf32(v1 - h1),
                                to_tf32(v2 - h2), to_tf32(v3 - h3));
    }
}

// ---------------------------------------------------------------------------
__global__ void xform_hl_kernel(const float* __restrict__ in, int ld,
                                float* __restrict__ oh, float* __restrict__ ol,
                                long long nrows, int K) {
    long long i = blockIdx.x * (long long)blockDim.x + threadIdx.x;
    int gpr = K / 16;
    if (i >= nrows * gpr) return;
    long long row = i / gpr;
    int grp = (int)(i - row * gpr);
    const float* src = in + (size_t)row * ld + grp * 16;
    float4 a[4];
    a[0] = ((const float4*)src)[0]; a[1] = ((const float4*)src)[1];
    a[2] = ((const float4*)src)[2]; a[3] = ((const float4*)src)[3];
    float* dh = oh + (size_t)row * K + grp * 16;
    float* dl = ol + (size_t)row * K + grp * 16;
    #pragma unroll
    for (int u = 0; u < 4; u++) {
        float v0 = (&a[0].x)[u], v1 = (&a[1].x)[u],
              v2 = (&a[2].x)[u], v3 = (&a[3].x)[u];
        float h0 = to_tf32(v0), h1 = to_tf32(v1),
              h2 = to_tf32(v2), h3 = to_tf32(v3);
        ((float4*)dh)[u] = make_float4(h0, h1, h2, h3);
        ((float4*)dl)[u] = make_float4(to_tf32(v0 - h0), to_tf32(v1 - h1),
                                       to_tf32(v2 - h2), to_tf32(v3 - h3));
    }
}

// ---------------------------------------------------------------------------
// cp.async 3-stage TF32 GEMM, 128x128 tile, 8 warps (R14 champion config).
// 256 threads, 2 blocks/SM (96KB smem each). K % 32 == 0.
// MODE: 0 bias+store, 2 qkv scatter (q/k/v tf32-rounded; K xform layout)
// ---------------------------------------------------------------------------
template<int MODE>
__global__ void __launch_bounds__(256, 2)
tc_gemm_async(const float* __restrict__ A, const float* __restrict__ B,
              const float* __restrict__ bias, float* __restrict__ C,
              int M, int N, int K)
{
    extern __shared__ float smx[];

    const int m0 = blockIdx.y * 128;
    const int n0 = blockIdx.x * 128;
    const int tid  = threadIdx.x;
    const int lane = tid & 31;
    const int w    = tid >> 5;
    const int wm = w >> 1, wn = w & 1;
    const int g  = lane >> 2, tg = lane & 3;
    const int m0w = wm * 32, n0w = wn * 64;

    const int crow = tid >> 3;
    const int cu   = tid & 7;
    const int fswz = ((g & 1) << 2) | (g & 3);

    float acc[2][8][4];
    #pragma unroll
    for (int i = 0; i < 2; i++)
        #pragma unroll
        for (int j = 0; j < 8; j++)
            #pragma unroll
            for (int r = 0; r < 4; r++) acc[i][j][r] = 0.f;

    auto issue = [&](int k0, int st) {
        float* sa = smx + st * 8192;
        float* sb = sa + 4096;
        #pragma unroll
        for (int i = 0; i < 4; i++) {
            int row = crow + 32 * i;
            int pu  = cu ^ (((row & 1) << 2) | (row & 3));
            int gm  = m0 + row;
            int gmc = gm < M ? gm : M - 1;
            cp_async16(smem_u32(sa + row * 32 + pu * 4),
                       A + (size_t)gmc * K + k0 + cu * 4, gm < M ? 16 : 0);
            int gn  = n0 + row;
            int gnc = gn < N ? gn : N - 1;
            cp_async16(smem_u32(sb + row * 32 + pu * 4),
                       B + (size_t)gnc * K + k0 + cu * 4, gn < N ? 16 : 0);
        }
        CP_COMMIT();
    };

    const int T = K / 32;
    issue(0, 0);
    issue(32, 1);
    for (int t = 0; t < T; t++) {
        if (t + 2 < T) issue((t + 2) * 32, (t + 2) % 3);
        else           CP_COMMIT();
        CP_WAIT2();
        __syncthreads();

        const float* sa = smx + (t % 3) * 8192;
        const float* sb = sa + 4096;
        #pragma unroll
        for (int gq = 0; gq < 2; gq++) {
            const int pu4 = ((4 * gq + tg) ^ fswz) * 4;
            float4 va[4];
            #pragma unroll
            for (int i = 0; i < 4; i++)
                va[i] = *(const float4*)(sa + (m0w + g + 8*i) * 32 + pu4);
            float4 vb[8];
            #pragma unroll
            for (int j = 0; j < 8; j++)
                vb[j] = *(const float4*)(sb + (n0w + 8*j + g) * 32 + pu4);

            #pragma unroll
            for (int i = 0; i < 2; i++) {
                uint32_t a0[4] = {
                    __float_as_uint(va[2*i].x), __float_as_uint(va[2*i+1].x),
                    __float_as_uint(va[2*i].y), __float_as_uint(va[2*i+1].y)};
                uint32_t a8[4] = {
                    __float_as_uint(va[2*i].z), __float_as_uint(va[2*i+1].z),
                    __float_as_uint(va[2*i].w), __float_as_uint(va[2*i+1].w)};
                #pragma unroll
                for (int j = 0; j < 8; j++) {
                    uint32_t b0[2] = {__float_as_uint(vb[j].x), __float_as_uint(vb[j].y)};
                    uint32_t b8[2] = {__float_as_uint(vb[j].z), __float_as_uint(vb[j].w)};
                    mma_tf32(acc[i][j], a0, b0);
                    mma_tf32(acc[i][j], a8, b8);
                }
            }
        }
        __syncthreads();
    }

    #pragma unroll
    for (int i = 0; i < 2; i++) {
        #pragma unroll
        for (int rr = 0; rr < 2; rr++) {
            const int gm = m0 + m0w + i*16 + g + rr*8;
            if (gm >= M) continue;
            if (MODE == 0) {
                float* crowp = C + (size_t)gm * N;
                #pragma unroll
                for (int j = 0; j < 8; j++) {
                    int gn = n0 + n0w + j*8 + tg*2;
                    crowp[gn]   = acc[i][j][rr*2]   + bias[gn];
                    crowp[gn+1] = acc[i][j][rr*2+1] + bias[gn+1];
                }
            } else {
                const int bb = gm / NV;
                const int nv = gm - bb * NV;
                const int qi = (nv == 0) ? 0 : (nv >= 65 ? nv - 64 : -1);
                float* kB = g_k + (size_t)bb * NH * NV * HD + (size_t)nv * HD;
                float* vB = g_v + (size_t)bb * NH * NV * HD + (size_t)nv * HD;
                float* qB = (qi >= 0)
                    ? g_q + (size_t)bb * NH * NQ * HD + (size_t)qi * HD : nullptr;
                #pragma unroll
                for (int j = 0; j < 8; j++) {
                    #pragma unroll
                    for (int e = 0; e < 2; e++) {
                        int gn = n0 + n0w + j*8 + tg*2 + e;
                        float t = to_tf32(acc[i][j][rr*2 + e] + bias[gn]);
                        int typ = gn / DIM;
                        int hd  = gn - typ * DIM;
                        int h = hd >> 6, d = hd & 63;
                        if (typ == 1) {
                            kB[(size_t)h * NV * HD + xfi(d)] = t;
                        } else if (typ == 2) {
                            vB[(size_t)h * NV * HD + d] = t;
                        } else if (qB) {
                            qB[(size_t)h * NQ * HD + d] = t;
                        }
                    }
                }
            }
        }
    }
}

// ---------------------------------------------------------------------------
// cp.async 2-stage 3xTF32 GEMM + GELU (unchanged from R14).
// ---------------------------------------------------------------------------
template<int HLOUT, int AGATHER>
__global__ void __launch_bounds__(256, 2)
tc_gemm3x_async(const float* __restrict__ Ah_, const float* __restrict__ Al_,
                const float* __restrict__ Bh_, const float* __restrict__ Bl_,
                const float* __restrict__ bias,
                float* __restrict__ C, float* __restrict__ ol,
                int M, int N, int K)
{
    extern __shared__ float smx[];

    const int m0 = blockIdx.y * 128;
    const int n0 = blockIdx.x * 128;
    const int tid  = threadIdx.x;
    const int lane = tid & 31;
    const int w    = tid >> 5;
    const int wm = w >> 1, wn = w & 1;
    const int g  = lane >> 2, tg = lane & 3;
    const int m0w = wm * 32, n0w = wn * 64;

    const int crow = tid >> 2;
    const int cu   = tid & 3;
    const int pu4  = (tg ^ (g & 3)) * 4;

    float acc[2][8][4];
    #pragma unroll
    for (int i = 0; i < 2; i++)
        #pragma unroll
        for (int j = 0; j < 8; j++)
            #pragma unroll
            for (int r = 0; r < 4; r++) acc[i][j][r] = 0.f;

    auto issue = [&](int k0, int st) {
        float* s_ah = smx + st * 8192;
        float* s_al = s_ah + 2048;
        float* s_bh = s_al + 2048;
        float* s_bl = s_bh + 2048;
        #pragma unroll
        for (int i = 0; i < 2; i++) {
            int row = crow + 64 * i;
            int pu  = cu ^ (row & 3);
            int gm  = m0 + row;
            size_t ahoff;
            if (AGATHER == 1) {
                int b = gm >> 8, s = gm & 255;
                ahoff = ((size_t)b * NV + 129 + s) * DIM + k0 + cu * 4;
            } else {
                ahoff = (size_t)gm * K + k0 + cu * 4;
            }
            size_t aloff = (size_t)gm * K + k0 + cu * 4;
            cp_async16(smem_u32(s_ah + row * 16 + pu * 4), Ah_ + ahoff, 16);
            cp_async16(smem_u32(s_al + row * 16 + pu * 4), Al_ + aloff, 16);
            int gn  = n0 + row;
            int gnc = gn < N ? gn : N - 1;
            int sz  = gn < N ? 16 : 0;
            size_t boff = (size_t)gnc * K + k0 + cu * 4;
            cp_async16(smem_u32(s_bh + row * 16 + pu * 4), Bh_ + boff, sz);
            cp_async16(smem_u32(s_bl + row * 16 + pu * 4), Bl_ + boff, sz);
        }
        CP_COMMIT();
    };

    const int T = K / 16;
    issue(0, 0);
    for (int t = 0; t < T; t++) {
        if (t + 1 < T) issue((t + 1) * 16, (t + 1) & 1);
        else           CP_COMMIT();
        CP_WAIT1();
        __syncthreads();

        const float* s    = smx + (t & 1) * 8192;
        const float* s_ah = s;
        const float* s_al = s + 2048;
        const float* s_bh = s + 4096;
        const float* s_bl = s + 6144;

        float4 vah[4], val_[4];
        #pragma unroll
        for (int i = 0; i < 4; i++) {
            int row = m0w + g + 8*i;
            vah[i]  = *(const float4*)(s_ah + row * 16 + pu4);
            val_[i] = *(const float4*)(s_al + row * 16 + pu4);
        }
        #pragma unroll
        for (int j = 0; j < 8; j++) {
            int row = n0w + j*8 + g;
            float4 vbh = *(const float4*)(s_bh + row * 16 + pu4);
            float4 vbl = *(const float4*)(s_bl + row * 16 + pu4);
            uint32_t bh0[2] = {__float_as_uint(vbh.x), __float_as_uint(vbh.y)};
            uint32_t bh8[2] = {__float_as_uint(vbh.z), __float_as_uint(vbh.w)};
            uint32_t bl0[2] = {__float_as_uint(vbl.x), __float_as_uint(vbl.y)};
            uint32_t bl8[2] = {__float_as_uint(vbl.z), __float_as_uint(vbl.w)};
            #pragma unroll
            for (int i = 0; i < 2; i++) {
                uint32_t ah0[4] = {
                    __float_as_uint(vah[2*i].x), __float_as_uint(vah[2*i+1].x),
                    __float_as_uint(vah[2*i].y), __float_as_uint(vah[2*i+1].y)};
                uint32_t ah8[4] = {
                    __float_as_uint(vah[2*i].z), __float_as_uint(vah[2*i+1].z),
                    __float_as_uint(vah[2*i].w), __float_as_uint(vah[2*i+1].w)};
                uint32_t al0[4] = {
                    __float_as_uint(val_[2*i].x), __float_as_uint(val_[2*i+1].x),
                    __float_as_uint(val_[2*i].y), __float_as_uint(val_[2*i+1].y)};
                uint32_t al8[4] = {
                    __float_as_uint(val_[2*i].z), __float_as_uint(val_[2*i+1].z),
                    __float_as_uint(val_[2*i].w), __float_as_uint(val_[2*i+1].w)};
                mma_tf32(acc[i][j], ah0, bl0);
                mma_tf32(acc[i][j], al0, bh0);
                mma_tf32(acc[i][j], ah0, bh0);
                mma_tf32(acc[i][j], ah8, bl8);
                mma_tf32(acc[i][j], al8, bh8);
                mma_tf32(acc[i][j], ah8, bh8);
            }
        }
        __syncthreads();
    }

    #pragma unroll
    for (int i = 0; i < 2; i++) {
        #pragma unroll
        for (int rr = 0; rr < 2; rr++) {
            int gm = m0 + m0w + i*16 + g + rr*8;
            if (gm >= M) continue;
            const float* brow = (HLOUT == 1) ? g_tb + (gm >> 8) * 384 : bias;
            #pragma unroll
            for (int j = 0; j < 8; j++) {
                #pragma unroll
                for (int e = 0; e < 2; e++) {
                    int gn = n0 + n0w + j*8 + tg*2 + e;
                    if (gn >= N) continue;
                    float t = gelu_exact(acc[i][j][rr*2+e] + brow[gn]);
                    if (HLOUT == 1) {
                        int dt = xfi(gn & 15) | (gn & ~15);
                        float th = to_tf32(t);
                        C [(size_t)gm * N + dt] = th;
                        ol[(size_t)gm * N + dt] = to_tf32(t - th);
                    } else {
                        C[(size_t)gm * N + gn] = t;
                    }
                }
            }
        }
    }
}

// ---------------------------------------------------------------------------
__global__ void tb_kernel(const float* __restrict__ dp1_w,
                          const float* __restrict__ dp1_b) {
    int b = blockIdx.x;
    int n = threadIdx.x;
    const float* tg = g_tgt + (size_t)b * DIM;
    const float* wr = dp1_w + (size_t)n * 1536 + DIM;
    float s = dp1_b[n];
    #pragma unroll 8
    for (int k = 0; k < DIM; k++)
        s = fmaf(tg[k], wr[k], s);
    g_tb[b * 384 + n] = s;
}

// ---------------------------------------------------------------------------
// Flash attention v4 (R15): cp.async staging + fused V column sums.
// ---------------------------------------------------------------------------
namespace {
constexpr int BQ = 128, BKV = 64;
}

struct FlashSmem {
    float Ks[BKV * HD];
    float Vs[BKV][HD + 4];
    float Ps[BKV][BQ + 4];
    int   km[BKV];
};

__global__ void __launch_bounds__(256, 2)
flash_kernel() {
    extern __shared__ char raw_smem[];
    FlashSmem& S = *reinterpret_cast<FlashSmem*>(raw_smem);

    const int bh = blockIdx.y;
    const int b  = bh / NH, h = bh % NH;
    const int q0 = blockIdx.x * BQ;
    const int tid  = threadIdx.x;
    const int lane = tid & 31;
    const int w    = tid >> 5;
    const int g  = lane >> 2, tg = lane & 3;
    const int mw = w * 16;
    const int* db = g_db + (size_t)b * SS;

    #pragma unroll
    for (int it = 0; it < 8; it++) {
        int idx = tid + it * 256;
        int q  = idx >> 4;
        int dc = (idx & 15) * 4;
        int gq = q0 + q;
        float4 v = make_float4(0.f, 0.f, 0.f, 0.f);
        if (gq < NQ)
            v = *(const float4*)(g_q + ((size_t)bh*NQ + gq)*HD + dc);
        S.Ps[dc+0][q] = v.x * ATT_SCALE;
        S.Ps[dc+1][q] = v.y * ATT_SCALE;
        S.Ps[dc+2][q] = v.z * ATT_SCALE;
        S.Ps[dc+3][q] = v.w * ATT_SCALE;
    }
    __syncthreads();

    uint32_t qa[8][4];
    #pragma unroll
    for (int s = 0; s < 8; s++) {
        int kk = s * 8;
        qa[s][0] = __float_as_uint(S.Ps[kk+tg  ][mw + g    ]);
        qa[s][1] = __float_as_uint(S.Ps[kk+tg  ][mw + g + 8]);
        qa[s][2] = __float_as_uint(S.Ps[kk+tg+4][mw + g    ]);
        qa[s][3] = __float_as_uint(S.Ps[kk+tg+4][mw + g + 8]);
    }

    const int r0 = q0 + mw + g, r1 = r0 + 8;
    const bool qT0 = (r0 >= 1 && r0 <= 64);
    const bool qT1 = (r1 >= 1 && r1 <= 64);
    const bool qP0 = (r0 >= 65 && r0 < NQ) ? (db[r0 - 65] != 0) : false;
    const bool qP1 = (r1 >= 65 && r1 < NQ) ? (db[r1 - 65] != 0) : false;

    float m0 = -INFINITY, m1 = -INFINITY, l0 = 0.f, l1 = 0.f;
    float accO[8][4];
    #pragma unroll
    for (int j = 0; j < 8; j++)
        #pragma unroll
        for (int r = 0; r < 4; r++) accO[j][r] = 0.f;

    const int vdcol = tid & 63;
    const int vrgrp = tid >> 6;
    float vreg = 0.f;

    for (int kt = 0; kt < 7; kt++) {
        __syncthreads();
        const int kbase = kt * BKV;
        #pragma unroll
        for (int it = 0; it < 4; it++) {
            int idx = tid + it * 256;
            int kv  = idx >> 4;
            int u   = idx & 15;
            int k   = kbase + kv;
            int kc  = (k < NV) ? k : NV - 1;
            int sz  = (k < NV) ? 16 : 0;
            int pu  = u ^ (kv & 7);
            cp_async16(smem_u32(S.Ks + kv * HD + pu * 4),
                       g_k + ((size_t)bh*NV + kc)*HD + u*4, sz);
            cp_async16(smem_u32(&S.Vs[kv][u*4]),
                       g_v + ((size_t)bh*NV + kc)*HD + u*4, sz);
        }
        CP_COMMIT();
        if (tid < BKV) {
            int k = kbase + tid;
            int fl = 0;
            if (k < NV) {
                fl = 4;
                if (k >= 1 && k <= 128) fl |= 1;
                if (k >= 129 && db[k - 129] != 0) fl |= 2;
            }
            S.km[tid] = fl;
        }
        CP_WAIT0();
        __syncthreads();

        {
            int kvmax = NV - kbase;
            #pragma unroll
            for (int rr2 = 0; rr2 < 16; rr2++) {
                int kv = vrgrp * 16 + rr2;
                if (kv < kvmax) vreg += S.Vs[kv][vdcol];
            }
        }

        float sacc[8][4];
        #pragma unroll
        for (int j = 0; j < 8; j++)
            #pragma unroll
            for (int r = 0; r < 4; r++) sacc[j][r] = 0.f;

        #pragma unroll
        for (int j = 0; j < 8; j++) {
            const int row = j*8 + g;
            const float* kr = S.Ks + row * HD;
            const int sw = row & 7;
            float4 kb[4];
            #pragma unroll
            for (int grp = 0; grp < 4; grp++)
                kb[grp] = *(const float4*)(kr + (((grp << 2) | tg) ^ sw) * 4);
            #pragma unroll
            for (int s = 0; s < 8; s++) {
                int grp = s >> 1;
                uint32_t b2[2];
                if (s & 1) {
                    b2[0] = __float_as_uint(kb[grp].z);
                    b2[1] = __float_as_uint(kb[grp].w);
                } else {
                    b2[0] = __float_as_uint(kb[grp].x);
                    b2[1] = __float_as_uint(kb[grp].y);
                }
                mma_tf32(sacc[j], qa[s], b2);
            }
        }

        int fA[8], fB[8];
        float tm0 = -INFINITY, tm1 = -INFINITY;
        #pragma unroll
        for (int j = 0; j < 8; j++) {
            int kvA = j*8 + 2*tg;
            fA[j] = S.km[kvA];
            fB[j] = S.km[kvA + 1];
            if (fA[j] & 4) { tm0 = fmaxf(tm0, sacc[j][0]); tm1 = fmaxf(tm1, sacc[j][2]); }
            if (fB[j] & 4) { tm0 = fmaxf(tm0, sacc[j][1]); tm1 = fmaxf(tm1, sacc[j][3]); }
        }
        #pragma unroll
        for (int o = 1; o <= 2; o <<= 1) {
            tm0 = fmaxf(tm0, __shfl_xor_sync(0xffffffffu, tm0, o));
            tm1 = fmaxf(tm1, __shfl_xor_sync(0xffffffffu, tm1, o));
        }
        float nm0 = fmaxf(m0, tm0), nm1 = fmaxf(m1, tm1);
        float f0 = __expf(m0 - nm0), f1 = __expf(m1 - nm1);

        float rs0 = 0.f, rs1 = 0.f;
        #pragma unroll
        for (int j = 0; j < 8; j++) {
            bool mA0 = (fA[j] & 4) && !((qT0 && (fA[j] & 2)) || (qP0 && (fA[j] & 1)));
            bool mB0 = (fB[j] & 4) && !((qT0 && (fB[j] & 2)) || (qP0 && (fB[j] & 1)));
            bool mA1 = (fA[j] & 4) && !((qT1 && (fA[j] & 2)) || (qP1 && (fA[j] & 1)));
            bool mB1 = (fB[j] & 4) && !((qT1 && (fB[j] & 2)) || (qP1 && (fB[j] & 1)));
            float e00 = mA0 ? __expf(sacc[j][0] - nm0) : 0.f;
            float e01 = mB0 ? __expf(sacc[j][1] - nm0) : 0.f;
            float e10 = mA1 ? __expf(sacc[j][2] - nm1) : 0.f;
            float e11 = mB1 ? __expf(sacc[j][3] - nm1) : 0.f;
            rs0 += e00 + e01;
            rs1 += e10 + e11;
            int kvA = j*8 + 2*tg;
            S.Ps[kvA    ][mw + g    ] = to_tf32(e00);
            S.Ps[kvA + 1][mw + g    ] = to_tf32(e01);
            S.Ps[kvA    ][mw + g + 8] = to_tf32(e10);
            S.Ps[kvA + 1][mw + g + 8] = to_tf32(e11);
        }
        #pragma unroll
        for (int o = 1; o <= 2; o <<= 1) {
            rs0 += __shfl_xor_sync(0xffffffffu, rs0, o);
            rs1 += __shfl_xor_sync(0xffffffffu, rs1, o);
        }
        l0 = l0 * f0 + rs0;
        l1 = l1 * f1 + rs1;
        #pragma unroll
        for (int j = 0; j < 8; j++) {
            accO[j][0] *= f0; accO[j][1] *= f0;
            accO[j][2] *= f1; accO[j][3] *= f1;
        }
        m0 = nm0; m1 = nm1;
        __syncwarp();

        #pragma unroll
        for (int kk = 0; kk < BKV; kk += 8) {
            uint32_t a[4];
            a[0] = __float_as_uint(S.Ps[kk+tg  ][mw + g    ]);
            a[1] = __float_as_uint(S.Ps[kk+tg  ][mw + g + 8]);
            a[2] = __float_as_uint(S.Ps[kk+tg+4][mw + g    ]);
            a[3] = __float_as_uint(S.Ps[kk+tg+4][mw + g + 8]);
            #pragma unroll
            for (int j = 0; j < 8; j++) {
                uint32_t b2[2] = {
                    __float_as_uint(S.Vs[kk+tg  ][j*8 + g]),
                    __float_as_uint(S.Vs[kk+tg+4][j*8 + g])};
                mma_tf32(accO[j], a, b2);
            }
        }
    }

    __syncthreads();
    float* vps = (float*)S.Ps;
    vps[vrgrp * 64 + vdcol] = vreg;
    __syncthreads();

    const float inv0 = 1.f / (l0 + EPS);
    const float inv1 = 1.f / (l1 + EPS);
    const float c = EPS / (float)NQ;
    #pragma unroll
    for (int j = 0; j < 8; j++) {
        #pragma unroll
        for (int r = 0; r < 4; r++) {
            int d = j*8 + 2*tg + (r & 1);
            int q = q0 + mw + g + ((r & 2) ? 8 : 0);
            if (q >= NQ) continue;
            float vs = vps[d] + vps[64 + d] + vps[128 + d] + vps[192 + d];
            float val = (accO[j][r] + c * vs) * ((r & 2) ? inv1 : inv0);
            int dt = xfi(d);
            g_ao[((size_t)b*NQ + q)*DIM + h*HD + dt] = to_tf32(val);
        }
    }
}

// ---------------------------------------------------------------------------
__global__ void mean_kernel(const float* __restrict__ x) {
    int b = blockIdx.x;
    int c = threadIdx.x;
    float s = 0.f;
    #pragma unroll 8
    for (int t = 0; t < 64; t++)
        s += x[((size_t)b*NV + 65 + t)*DIM + c];
    g_tgt[b*DIM + c] = s * (1.0f/64.0f);
}

__global__ void mlp3_kernel(const float* __restrict__ w3,
                            const float* __restrict__ b3) {
    int gwarp = (blockIdx.x * blockDim.x + threadIdx.x) >> 5;
    int lane  = threadIdx.x & 31;
    if (gwarp >= TOKENS) return;
    const float* row = g_h2 + (size_t)gwarp * 192;
    float s0 = 0.f, s1 = 0.f;
    for (int k = lane; k < 192; k += 32) {
        float xv = row[k];
        s0 = fmaf(xv, w3[k],       s0);
        s1 = fmaf(xv, w3[192 + k], s1);
    }
    #pragma unroll
    for (int o = 16; o; o >>= 1) {
        s0 += __shfl_xor_sync(0xffffffffu, s0, o);
        s1 += __shfl_xor_sync(0xffffffffu, s1, o);
    }
    if (lane == 0)
        g_db[gwarp] = (s0 + b3[0] >= s1 + b3[1]) ? 1 : 0;
}

// ---------------------------------------------------------------------------
extern "C" void kernel_launch(void* const* d_in, const int* in_sizes, int n_in,
                              void* d_out, int out_size) {
    const float* x      = (const float*)d_in[0];
    const float* qkv_w  = (const float*)d_in[2];
    const float* qkv_b  = (const float*)d_in[3];
    const float* proj_w = (const float*)d_in[4];
    const float* proj_b = (const float*)d_in[5];
    const float* dp1_w  = (const float*)d_in[6];
    const float* dp1_b  = (const float*)d_in[7];
    const float* dp2_w  = (const float*)d_in[8];
    const float* dp2_b  = (const float*)d_in[9];
    const float* dp3_w  = (const float*)d_in[10];
    const float* dp3_b  = (const float*)d_in[11];
    float* out = (float*)d_out;

    float *p_h2, *p_ao, *p_xt, *p_qwt, *p_pwt;
    float *p_xsl, *p_w1h, *p_w1l, *p_h1h, *p_h1l, *p_w2h, *p_w2l;
    cudaGetSymbolAddress((void**)&p_h2,  g_h2);
    cudaGetSymbolAddress((void**)&p_ao,  g_ao);
    cudaGetSymbolAddress((void**)&p_xt,  g_xt);
    cudaGetSymbolAddress((void**)&p_qwt, g_qwt);
    cudaGetSymbolAddress((void**)&p_pwt, g_pwt);
    cudaGetSymbolAddress((void**)&p_xsl, g_xsl);
    cudaGetSymbolAddress((void**)&p_w1h, g_w1h);
    cudaGetSymbolAddress((void**)&p_w1l, g_w1l);
    cudaGetSymbolAddress((void**)&p_h1h, g_h1h);
    cudaGetSymbolAddress((void**)&p_h1l, g_h1l);
    cudaGetSymbolAddress((void**)&p_w2h, g_w2h);
    cudaGetSymbolAddress((void**)&p_w2l, g_w2l);

    auto cdiv = [](int a, int b) { return (a + b - 1) / b; };

    constexpr int SMEMAS3 = 3 * 8192 * 4;
    constexpr int SMEM3XA = 2 * 8192 * 4;
    cudaFuncSetAttribute(tc_gemm_async<2>,
                         cudaFuncAttributeMaxDynamicSharedMemorySize, SMEMAS3);
    cudaFuncSetAttribute(tc_gemm_async<0>,
                         cudaFuncAttributeMaxDynamicSharedMemorySize, SMEMAS3);
    cudaFuncSetAttribute((const void*)tc_gemm3x_async<1,1>,
                         cudaFuncAttributeMaxDynamicSharedMemorySize, SMEM3XA);
    cudaFuncSetAttribute((const void*)tc_gemm3x_async<0,0>,
                         cudaFuncAttributeMaxDynamicSharedMemorySize, SMEM3XA);
    cudaFuncSetAttribute(flash_kernel,
                         cudaFuncAttributeMaxDynamicSharedMemorySize,
                         (int)sizeof(FlashSmem));

    {
        long long gx = (long long)B_ * NV * (DIM / 16);
        xform_x_kernel<<<(unsigned)cdiv((int)gx, 256), 256>>>(x, p_xt, p_xsl);
        long long gw = (long long)QKVD * (DIM / 16);
        xform_kernel<<<(unsigned)cdiv((int)gw, 256), 256>>>(qkv_w, p_qwt, gw);
        long long gp = (long long)DIM * (DIM / 16);
        xform_kernel<<<(unsigned)cdiv((int)gp, 256), 256>>>(proj_w, p_pwt, gp);
        long long g1 = 384LL * (DIM / 16);
        xform_hl_kernel<<<(unsigned)cdiv((int)g1, 256), 256>>>(
            dp1_w, 1536, p_w1h, p_w1l, 384, DIM);
        long long g2 = 192LL * (384 / 16);
        xform_hl_kernel<<<(unsigned)cdiv((int)g2, 256), 256>>>(
            dp2_w, 384, p_w2h, p_w2l, 192, 384);
    }

    mean_kernel<<<B_, DIM>>>(x);
    tb_kernel<<<B_, 384>>>(dp1_w, dp1_b);
    tc_gemm3x_async<1,1><<<dim3(3, TOKENS/128), 256, SMEM3XA>>>(
        p_xt, p_xsl, p_w1h, p_w1l, nullptr, p_h1h, p_h1l, TOKENS, 384, DIM);
    tc_gemm3x_async<0,0><<<dim3(2, TOKENS/128), 256, SMEM3XA>>>(
        p_h1h, p_h1l, p_w2h, p_w2l, dp2_b, p_h2, nullptr, TOKENS, 192, 384);
    mlp3_kernel<<<cdiv(TOKENS*32, 256), 256>>>(dp3_w, dp3_b);

    // QKV projection + head scatter (8-warp 128x128, 3-stage, 2 blocks/SM)
    tc_gemm_async<2><<<dim3(QKVD/128, cdiv(B_*NV,128)), 256, SMEMAS3>>>(
        p_xt, p_qwt, qkv_b, nullptr, B_*NV, QKVD, DIM);

    // fused attention (includes V column sums)
    flash_kernel<<<dim3(cdiv(NQ, BQ), BH), 256, sizeof(FlashSmem)>>>();

    // output projection
    tc_gemm_async<0><<<dim3(DIM/128, cdiv(B_*NQ,128)), 256, SMEMAS3>>>(
        p_ao, p_pwt, proj_b, out, B_*NQ, DIM, DIM);
}